// round 2
// baseline (speedup 1.0000x reference)
#include <cuda_runtime.h>
#include <math.h>

// ---------------- problem constants (static in reference) ----------------
#define N_SAMPLES 4410000
#define WSZ       441          // wavetable size = SR // 100
#define NCHUNK    10000        // N_SAMPLES / WSZ (no remainder)
#define BB        80           // chunks per block
#define GG        125          // number of blocks (BB*GG == NCHUNK)

#define PI_F      3.14159265358979f
#define TWOPI_F   6.2831853071795864f
#define SR_F      44100.0f

// ---------------- device scratch (no runtime allocation allowed) ----------
__device__ float g_ct[WSZ];            // cos(2*pi*j/441)
__device__ float g_st[WSZ];            // sin(2*pi*j/441)
__device__ float g_what[2 * WSZ];      // DFT of wavetable (initial state)
__device__ float g_lamB[2 * WSZ];      // lambda_m ^ BB
__device__ float g_Ehat[GG * 2 * WSZ]; // per-block forced end-state spectra
__device__ float g_Shat[GG * 2 * WSZ]; // per-block entering-state spectra
__device__ float g_scal[8];            // 0:c 1:fa 2:A4 3:a 4:s 5:r 6:T 7:decay

// ---------------- sequential biquad (direct form II transposed) ----------
// Matches reference biquad_lowpass exactly (fp32 ops, same ordering).
__device__ __forceinline__ void biquad_seq(const float* __restrict__ x,
                                           float* __restrict__ y,
                                           int n, float f, float q) {
    float w0   = (TWOPI_F * f) / SR_F;
    float cosw = cosf(w0);
    float alpha = sinf(w0) / (2.0f * q);
    float b0 = (1.0f - cosw) / 2.0f;
    float b1 = 1.0f - cosw;
    float b2 = (1.0f - cosw) / 2.0f;
    float a0 = 1.0f + alpha;
    float a1 = -2.0f * cosw;
    float a2 = 1.0f - alpha;
    b0 /= a0; b1 /= a0; b2 /= a0; a1 /= a0; a2 /= a0;
    float s1 = 0.0f, s2 = 0.0f;
    for (int i = 0; i < n; i++) {
        float xn = x[i];
        float yv = b0 * xn + s1;
        float s1n = b1 * xn - a1 * yv + s2;
        float s2n = b2 * xn - a2 * yv;
        s1 = s1n; s2 = s2n;
        y[i] = yv;
    }
}

// ---------------- K1: setup (MLP, biquads, twiddles, what, lamB) ---------
__global__ __launch_bounds__(448)
void k_setup(const float* __restrict__ h,  const float* __restrict__ noise,
             const float* __restrict__ W1, const float* __restrict__ b1,
             const float* __restrict__ W2, const float* __restrict__ b2,
             const float* __restrict__ lp, const float* __restrict__ env) {
    __shared__ float sh_hidden[128];
    __shared__ float sh_lat[5];
    __shared__ float sh_tmp[WSZ];
    __shared__ float sh_wt[WSZ];
    __shared__ float sh_ct[WSZ];
    __shared__ float sh_st[WSZ];
    __shared__ float sh_dec;
    int tid = threadIdx.x;

    if (tid < WSZ) {
        float ang = (TWOPI_F * (float)tid) / 441.0f;
        float sv, cv;
        sincosf(ang, &sv, &cv);
        g_ct[tid] = cv; g_st[tid] = sv;
        sh_ct[tid] = cv; sh_st[tid] = sv;
    }

    // MLP: relu(relu(h@W1 + b1) @ W2 + b2)
    if (tid < 128) {
        float acc = b1[tid];
        #pragma unroll
        for (int i = 0; i < 9; i++) acc += h[i] * W1[i * 128 + tid];
        sh_hidden[tid] = fmaxf(acc, 0.0f);
    }
    __syncthreads();
    if (tid < 5) {
        float acc = b2[tid];
        for (int j = 0; j < 128; j++) acc += sh_hidden[j] * W2[j * 5 + tid];
        sh_lat[tid] = fmaxf(acc, 0.0f);
    }
    __syncthreads();

    if (tid == 0) {
        float l0 = sh_lat[0], l1 = sh_lat[1], l2 = sh_lat[2];
        float l3 = sh_lat[3], l4 = sh_lat[4];
        float decay = fminf(fmaxf(l0 / 10.0f + 0.9f, 0.9f), 0.999f);
        float lpf = fminf(fmaxf(l1 * SR_F / 4.0f, 100.0f), SR_F / 2.0f - 1.0f);
        float lpq = fminf(fmaxf(l2, 0.1f), 0.999f);
        biquad_seq(noise, sh_tmp, WSZ, lpf, lpq);
        biquad_seq(sh_tmp, sh_wt, WSZ, lp[0], 0.707f);
        sh_dec = decay;
        g_scal[0] = decay * 0.5f;                  // c
        g_scal[1] = l3;                            // feedbackamt
        g_scal[2] = l4;                            // output gain
        g_scal[3] = fabsf(env[0]) + 1e-3f;         // attack
        g_scal[4] = env[1];                        // sustain
        g_scal[5] = fabsf(env[2]) + 1e-3f;         // release
        g_scal[6] = (float)(N_SAMPLES - 1) / SR_F; // T == t[-1] exactly (fp32)
        g_scal[7] = decay;
    }
    __syncthreads();

    if (tid < WSZ) {
        int m = tid;
        // forward DFT of wavetable
        float re = 0.0f, im = 0.0f;
        int idx = 0;
        for (int i = 0; i < WSZ; i++) {
            float v = sh_wt[i];
            re = fmaf(v, sh_ct[idx], re);
            im = fmaf(-v, sh_st[idx], im);
            idx += m; if (idx >= WSZ) idx -= WSZ;
        }
        g_what[2 * m]     = re;
        g_what[2 * m + 1] = im;
        // lambda_m^BB : lambda = decay*cos(pi m/441) * e^{-i pi m/441}; BB even
        float dec = sh_dec;
        float rr  = dec * cosf((PI_F * (float)m) / 441.0f);
        float mag = powf(fabsf(rr), (float)BB);
        int   k2  = (BB * m) % (2 * WSZ);
        float angp = -(PI_F * (float)k2) / 441.0f;
        float sp, cp;
        sincosf(angp, &sp, &cp);
        g_lamB[2 * m]     = mag * cp;
        g_lamB[2 * m + 1] = mag * sp;
    }
}

// ---------------- K2: pass A — block forced responses + forward DFT ------
__global__ __launch_bounds__(448)
void k_passA(const float* __restrict__ fb) {
    extern __shared__ float sm[];
    float* sfb = sm;                       // BB*WSZ
    float* sct = sm + BB * WSZ;            // WSZ
    float* sst = sct + WSZ;                // WSZ
    float* sx  = sst + WSZ;                // 2*WSZ (double buffer)
    float* se  = sx + 2 * WSZ;             // WSZ

    int tid = threadIdx.x;
    int g   = blockIdx.x;
    const float* fbg = fb + (size_t)g * BB * WSZ;
    for (int idx = tid; idx < BB * WSZ; idx += blockDim.x) sfb[idx] = fbg[idx];
    if (tid < WSZ) { sct[tid] = g_ct[tid]; sst[tid] = g_st[tid]; }
    float c  = g_scal[0];
    float fa = g_scal[1];
    __syncthreads();

    int i   = tid;
    int im1 = (i == 0) ? (WSZ - 1) : (i - 1);
    float cur = 0.0f;
    for (int b = 0; b < BB; b++) {
        float x = fmaf(fa, sfb[b * WSZ + i], cur);
        float* buf = sx + (b & 1) * WSZ;
        buf[i] = x;
        __syncthreads();
        cur = c * (x + buf[im1]);
    }
    se[i] = cur;
    __syncthreads();

    // forward DFT of block end state
    {
        int m = tid;
        float re = 0.0f, im = 0.0f;
        int idx = 0;
        for (int ii = 0; ii < WSZ; ii++) {
            float v = se[ii];
            re = fmaf(v, sct[idx], re);
            im = fmaf(-v, sst[idx], im);
            idx += m; if (idx >= WSZ) idx -= WSZ;
        }
        size_t base = (size_t)g * 2 * WSZ;
        g_Ehat[base + 2 * m]     = re;
        g_Ehat[base + 2 * m + 1] = im;
    }
}

// ---------------- K3: tiny sequential scan over blocks (per bin) ---------
__global__ __launch_bounds__(448)
void k_scan() {
    int m = threadIdx.x;
    if (m >= WSZ) return;
    float sre = g_what[2 * m], sim = g_what[2 * m + 1];
    float lre = g_lamB[2 * m], lim = g_lamB[2 * m + 1];
    for (int g = 0; g < GG; g++) {
        size_t base = (size_t)g * 2 * WSZ;
        g_Shat[base + 2 * m]     = sre;
        g_Shat[base + 2 * m + 1] = sim;
        float ere = g_Ehat[base + 2 * m];
        float eim = g_Ehat[base + 2 * m + 1];
        float nre = lre * sre - lim * sim + ere;
        float nim = lre * sim + lim * sre + eim;
        sre = nre; sim = nim;
    }
}

// ---------------- K4: pass B — iDFT entering state, emit finished output --
// (envelope, fade and output gain fused into the store)
__global__ __launch_bounds__(448)
void k_passB(const float* __restrict__ fb, const float* __restrict__ fade,
             float* __restrict__ out) {
    extern __shared__ float sm[];
    float* sfb = sm;                       // BB*WSZ
    float* sct = sm + BB * WSZ;            // WSZ
    float* sst = sct + WSZ;                // WSZ
    float* sx  = sst + WSZ;                // 2*WSZ
    float* ssp = sx + 2 * WSZ;             // 2*WSZ (spectrum, interleaved)

    int tid = threadIdx.x;
    int g   = blockIdx.x;
    const float* fbg = fb + (size_t)g * BB * WSZ;
    for (int idx = tid; idx < BB * WSZ; idx += blockDim.x) sfb[idx] = fbg[idx];
    if (tid < WSZ) { sct[tid] = g_ct[tid]; sst[tid] = g_st[tid]; }
    {
        size_t base = (size_t)g * 2 * WSZ;
        for (int idx = tid; idx < 2 * WSZ; idx += blockDim.x) ssp[idx] = g_Shat[base + idx];
    }
    float c  = g_scal[0];
    float fa = g_scal[1];
    float A4 = g_scal[2];
    float a  = g_scal[3];
    float s  = g_scal[4];
    float r  = g_scal[5];
    float T  = g_scal[6];
    __syncthreads();

    // inverse DFT: entering state sample i
    int i = tid;
    float acc = 0.0f;
    int idx = 0;
    for (int m = 0; m < WSZ; m++) {
        acc = fmaf(ssp[2 * m],      sct[idx], acc);
        acc = fmaf(-ssp[2 * m + 1], sst[idx], acc);
        idx += i; if (idx >= WSZ) idx -= WSZ;
    }
    float cur = acc * (1.0f / 441.0f);

    int im1 = (i == 0) ? (WSZ - 1) : (i - 1);
    float* og = out + (size_t)g * BB * WSZ;
    int nbase = g * BB * WSZ + i;
    for (int b = 0; b < BB; b++) {
        float x = fmaf(fa, sfb[b * WSZ + i], cur);
        float* buf = sx + (b & 1) * WSZ;
        buf[i] = x;
        __syncthreads();
        cur = c * (x + buf[im1]);

        // fused epilogue: fade (last 256 samples), ASR envelope, output gain
        int n = nbase + b * WSZ;
        float v = cur;
        if (n >= N_SAMPLES - 256) v *= fade[n - (N_SAMPLES - 256)];
        float tn = (float)n / SR_F;                    // == t[n] exactly in fp32
        float e1 = fminf(fmaxf(tn / a, 0.0f), 1.0f);
        float e2 = fminf(fmaxf((T - tn) / r, 0.0f), 1.0f);
        float envv = e1 * e2 * s;
        og[b * WSZ + i] = v * envv * A4;
    }
}

// ---------------- host entry --------------------------------------------
extern "C" void kernel_launch(void* const* d_in, const int* in_sizes, int n_in,
                              void* d_out, int out_size) {
    const float* fb    = (const float*)d_in[0];   // feedback_line [4410000]
    const float* h     = (const float*)d_in[1];   // h [1,9]
    // d_in[2] = t [4410000] — not needed, t[n] == n/44100 exactly in fp32
    const float* noise = (const float*)d_in[3];   // wavetable_noise [441]
    const float* W1    = (const float*)d_in[4];   // [9,128]
    const float* b1    = (const float*)d_in[5];   // [128]
    const float* W2    = (const float*)d_in[6];   // [128,5]
    const float* b2    = (const float*)d_in[7];   // [5]
    const float* lp    = (const float*)d_in[8];   // lp_cutoff [1]
    const float* env   = (const float*)d_in[9];   // env_params [3]
    const float* fade  = (const float*)d_in[10];  // fade [256]
    float* out = (float*)d_out;

    const int dsA = (BB * WSZ + 4 * WSZ + WSZ) * (int)sizeof(float);   // 149,940 B
    const int dsB = (BB * WSZ + 6 * WSZ)       * (int)sizeof(float);   // 151,704 B
    cudaFuncSetAttribute(k_passA, cudaFuncAttributeMaxDynamicSharedMemorySize, dsA);
    cudaFuncSetAttribute(k_passB, cudaFuncAttributeMaxDynamicSharedMemorySize, dsB);

    k_setup<<<1, WSZ>>>(h, noise, W1, b1, W2, b2, lp, env);
    k_passA<<<GG, WSZ, dsA>>>(fb);
    k_scan<<<1, WSZ>>>();
    k_passB<<<GG, WSZ, dsB>>>(fb, fade, out);
}

// round 3
// speedup vs baseline: 1.8047x; 1.8047x over previous
#include <cuda_runtime.h>
#include <math.h>

// ---------------- problem constants (static in reference) ----------------
#define N_SAMPLES 4410000
#define WSZ       441          // wavetable size
#define NCHUNK    10000        // N_SAMPLES / WSZ
#define BB        80           // chunks per block
#define GG        125          // number of blocks (BB*GG == NCHUNK)
#define NBIN      221          // Hermitian bins 0..220 (441 odd -> no Nyquist)

#define PI_F      3.14159265358979f
#define TWOPI_F   6.2831853071795864f
#define SR_F      44100.0f

// ---------------- device scratch --------------------------------------
__device__ float g_what[2 * NBIN];      // DFT of wavetable (bins 0..220)
__device__ float g_lamB[2 * NBIN];      // lambda_m ^ BB
__device__ float g_Ehat[GG * 2 * NBIN]; // per-block forced end-state spectra
__device__ float g_Shat[GG * 2 * NBIN]; // per-block entering-state spectra
__device__ float g_scal[8];             // 0:c 1:fa 2:A4 3:inv_a 4:s 5:inv_r 6:T 7:decay

// ---------------- parallel biquad via affine scan -----------------------
// State v=(s1,s2): v_{n+1} = M v_n + x_n*d,  y_n = b0*x_n + s1_n, v_0=0.
// M = [[-a1,1],[-a2,0]] constant -> Hillis-Steele level-d multiplier = M^(2^d).
__device__ void biquad_par(const float* __restrict__ x, float* __restrict__ y,
                           float f, float q, int tid,
                           float* sb1, float* sb2, float (*sMp)[4]) {
    float w0   = (TWOPI_F * f) / SR_F;
    float cosw = cosf(w0);
    float alpha = sinf(w0) / (2.0f * q);
    float b0 = (1.0f - cosw) / 2.0f;
    float b1c = 1.0f - cosw;
    float b2c = (1.0f - cosw) / 2.0f;
    float a0 = 1.0f + alpha;
    float a1 = -2.0f * cosw;
    float a2 = 1.0f - alpha;
    b0 /= a0; b1c /= a0; b2c /= a0; a1 /= a0; a2 /= a0;
    float d1 = b1c - a1 * b0;
    float d2 = b2c - a2 * b0;

    if (tid == 0) {
        float A0 = -a1, A1 = 1.0f, A2 = -a2, A3 = 0.0f;
        #pragma unroll
        for (int dd = 0; dd < 9; dd++) {
            sMp[dd][0] = A0; sMp[dd][1] = A1; sMp[dd][2] = A2; sMp[dd][3] = A3;
            float n0 = A0 * A0 + A1 * A2;
            float n1 = A0 * A1 + A1 * A3;
            float n2 = A2 * A0 + A3 * A2;
            float n3 = A2 * A1 + A3 * A3;
            A0 = n0; A1 = n1; A2 = n2; A3 = n3;
        }
    }
    float xv = x[tid];
    sb1[tid] = xv * d1;
    sb2[tid] = xv * d2;
    __syncthreads();
    #pragma unroll
    for (int dd = 0; dd < 9; dd++) {
        int off = 1 << dd;
        float p1 = 0.0f, p2 = 0.0f;
        if (tid >= off) { p1 = sb1[tid - off]; p2 = sb2[tid - off]; }
        float m0 = sMp[dd][0], m1 = sMp[dd][1], m2 = sMp[dd][2], m3 = sMp[dd][3];
        __syncthreads();
        if (tid >= off) {
            sb1[tid] = fmaf(m0, p1, fmaf(m1, p2, sb1[tid]));
            sb2[tid] = fmaf(m2, p1, fmaf(m3, p2, sb2[tid]));
        }
        __syncthreads();
    }
    float s1 = (tid == 0) ? 0.0f : sb1[tid - 1];
    y[tid] = fmaf(b0, xv, s1);
    __syncthreads();
}

// ---------------- K1: setup (MLP, biquads, what, lamB, scalars) ----------
__global__ __launch_bounds__(WSZ)
void k_setup(const float* __restrict__ h,  const float* __restrict__ noise,
             const float* __restrict__ W1, const float* __restrict__ b1,
             const float* __restrict__ W2, const float* __restrict__ b2,
             const float* __restrict__ lp, const float* __restrict__ env) {
    __shared__ float sh_hidden[128];
    __shared__ float sh_lat[5];
    __shared__ float sx[WSZ];
    __shared__ float sy[WSZ];
    __shared__ float sb1[WSZ];
    __shared__ float sb2[WSZ];
    __shared__ float sMp[9][4];
    int tid = threadIdx.x;

    // MLP: relu(relu(h@W1 + b1) @ W2 + b2)
    if (tid < 128) {
        float acc = b1[tid];
        #pragma unroll
        for (int i = 0; i < 9; i++) acc += h[i] * W1[i * 128 + tid];
        sh_hidden[tid] = fmaxf(acc, 0.0f);
    }
    sx[tid] = noise[tid];
    __syncthreads();
    if (tid < 5) {
        float acc = b2[tid];
        for (int j = 0; j < 128; j++) acc += sh_hidden[j] * W2[j * 5 + tid];
        sh_lat[tid] = fmaxf(acc, 0.0f);
    }
    __syncthreads();

    float l0 = sh_lat[0], l1 = sh_lat[1], l2 = sh_lat[2];
    float l3 = sh_lat[3], l4 = sh_lat[4];
    float decay = fminf(fmaxf(l0 / 10.0f + 0.9f, 0.9f), 0.999f);
    float lpf = fminf(fmaxf(l1 * SR_F / 4.0f, 100.0f), SR_F / 2.0f - 1.0f);
    float lpq = fminf(fmaxf(l2, 0.1f), 0.999f);

    // two cascaded biquads, parallel scan
    biquad_par(sx, sy, lpf, lpq, tid, sb1, sb2, sMp);
    biquad_par(sy, sx, lp[0], 0.707f, tid, sb1, sb2, sMp);
    // sx now holds the wavetable wt

    if (tid == 0) {
        g_scal[0] = decay * 0.5f;                   // c
        g_scal[1] = l3;                             // feedbackamt
        g_scal[2] = l4;                             // output gain
        g_scal[3] = 1.0f / (fabsf(env[0]) + 1e-3f); // 1/attack
        g_scal[4] = env[1];                         // sustain
        g_scal[5] = 1.0f / (fabsf(env[2]) + 1e-3f); // 1/release
        g_scal[6] = (float)(N_SAMPLES - 1) / SR_F;  // T == t[-1] exactly (fp32)
        g_scal[7] = decay;
    }

    // forward DFT of wt, Hermitian bins 0..220, split-half rotation
    {
        int  m     = (tid <= 220) ? tid : (tid - 221);
        int  start = (tid <= 220) ? 0 : 221;
        int  cnt   = (tid <= 220) ? 221 : 220;
        float theta = -(TWOPI_F * (float)m) / 441.0f;
        float c0, s0; sincosf(theta, &s0, &c0);
        float wc, ws; sincosf(theta * (float)start, &ws, &wc);
        float re = 0.0f, im = 0.0f;
        for (int k = 0; k < cnt; k++) {
            float v = sx[start + k];
            re = fmaf(v, wc, re);
            im = fmaf(v, ws, im);
            float nwc = wc * c0 - ws * s0;
            ws = fmaf(wc, s0, ws * c0);
            wc = nwc;
        }
        sb1[tid] = re; sb2[tid] = im;
        __syncthreads();
        if (tid <= 220) {
            float Re = re + ((tid < 220) ? sb1[tid + 221] : 0.0f);
            float Im = im + ((tid < 220) ? sb2[tid + 221] : 0.0f);
            g_what[2 * tid]     = Re;
            g_what[2 * tid + 1] = Im;
            // lambda_m^BB : lambda = decay*cos(pi m/441) * e^{-i pi m/441}
            float rr  = decay * cosf((PI_F * (float)tid) / 441.0f); // > 0 for m<=220
            float mag = powf(rr, (float)BB);
            int   k2  = (BB * tid) % (2 * WSZ);
            float angp = -(PI_F * (float)k2) / 441.0f;
            float sp, cp; sincosf(angp, &sp, &cp);
            g_lamB[2 * tid]     = mag * cp;
            g_lamB[2 * tid + 1] = mag * sp;
        }
    }
}

// ---------------- K2: pass A — block forced responses + forward DFT ------
__global__ __launch_bounds__(WSZ)
void k_passA(const float* __restrict__ fb) {
    extern __shared__ float sm[];
    float* sfb = sm;                       // BB*WSZ
    float* sx  = sm + BB * WSZ;            // 2*WSZ (double buffer; later DFT partials)
    float* se  = sx + 2 * WSZ;             // WSZ

    int tid = threadIdx.x;
    int g   = blockIdx.x;
    const float* fbg = fb + (size_t)g * BB * WSZ;
    #pragma unroll 4
    for (int b = 0; b < BB; b++) sfb[b * WSZ + tid] = fbg[b * WSZ + tid];
    float c  = g_scal[0];
    float fa = g_scal[1];
    __syncthreads();

    int i   = tid;
    int im1 = (i == 0) ? (WSZ - 1) : (i - 1);
    float cur = 0.0f;
    for (int b = 0; b < BB; b++) {
        float x = fmaf(fa, sfb[b * WSZ + i], cur);
        float* buf = sx + (b & 1) * WSZ;
        buf[i] = x;
        __syncthreads();
        cur = c * (x + buf[im1]);
    }
    se[i] = cur;
    __syncthreads();

    // forward DFT of block end state (Hermitian, split-half, rotation)
    {
        int  m     = (tid <= 220) ? tid : (tid - 221);
        int  start = (tid <= 220) ? 0 : 221;
        int  cnt   = (tid <= 220) ? 221 : 220;
        float theta = -(TWOPI_F * (float)m) / 441.0f;
        float c0, s0; sincosf(theta, &s0, &c0);
        float wc, ws; sincosf(theta * (float)start, &ws, &wc);
        float re = 0.0f, im = 0.0f;
        for (int k = 0; k < cnt; k++) {
            float v = se[start + k];
            re = fmaf(v, wc, re);
            im = fmaf(v, ws, im);
            float nwc = wc * c0 - ws * s0;
            ws = fmaf(wc, s0, ws * c0);
            wc = nwc;
        }
        sx[tid] = re; sx[WSZ + tid] = im;
        __syncthreads();
        if (tid <= 220) {
            float Re = re + ((tid < 220) ? sx[tid + 221] : 0.0f);
            float Im = im + ((tid < 220) ? sx[WSZ + tid + 221] : 0.0f);
            size_t base = (size_t)g * 2 * NBIN;
            g_Ehat[base + 2 * tid]     = Re;
            g_Ehat[base + 2 * tid + 1] = Im;
        }
    }
}

// ---------------- K3: tiny sequential scan over blocks (per bin) ---------
__global__ __launch_bounds__(256)
void k_scan() {
    int m = blockIdx.x * blockDim.x + threadIdx.x;
    if (m >= NBIN) return;
    float sre = g_what[2 * m], sim = g_what[2 * m + 1];
    float lre = g_lamB[2 * m], lim = g_lamB[2 * m + 1];
    for (int g = 0; g < GG; g++) {
        size_t base = (size_t)g * 2 * NBIN;
        g_Shat[base + 2 * m]     = sre;
        g_Shat[base + 2 * m + 1] = sim;
        float ere = g_Ehat[base + 2 * m];
        float eim = g_Ehat[base + 2 * m + 1];
        float nre = lre * sre - lim * sim + ere;
        float nim = lre * sim + lim * sre + eim;
        sre = nre; sim = nim;
    }
}

// ---------------- K4: pass B — iDFT entering state, emit finished output --
__global__ __launch_bounds__(WSZ)
void k_passB(const float* __restrict__ fb, const float* __restrict__ fade,
             float* __restrict__ out) {
    extern __shared__ float sm[];
    float* sfb = sm;                       // BB*WSZ
    float* sx  = sm + BB * WSZ;            // 2*WSZ double buffer
    float* ssp = sx + 2 * WSZ;             // 2*NBIN spectrum (interleaved)

    int tid = threadIdx.x;
    int g   = blockIdx.x;
    const float* fbg = fb + (size_t)g * BB * WSZ;
    #pragma unroll 4
    for (int b = 0; b < BB; b++) sfb[b * WSZ + tid] = fbg[b * WSZ + tid];
    {
        size_t base = (size_t)g * 2 * NBIN;
        if (tid < 2 * NBIN) ssp[tid] = g_Shat[base + tid];
    }
    float c  = g_scal[0];
    float fa = g_scal[1];
    float A4 = g_scal[2];
    float inva = g_scal[3];
    float s  = g_scal[4];
    float invr = g_scal[5];
    float T  = g_scal[6];
    __syncthreads();

    // inverse DFT via Hermitian symmetry:
    // x[i] = (1/441) * ( X0 + 2*sum_{m=1..220} (Re_m cos(2pi m i/441) - Im_m sin(.)) )
    int i = tid;
    float cur;
    {
        float theta = (TWOPI_F * (float)i) / 441.0f;
        float c0, s0; sincosf(theta, &s0, &c0);
        float wc = c0, ws = s0;  // start at m=1
        float acc = 0.0f;
        const float2* sp2 = (const float2*)ssp;
        for (int m = 1; m <= 220; m++) {
            float2 X = sp2[m];   // broadcast across the warp
            acc = fmaf(X.x, wc, acc);
            acc = fmaf(-X.y, ws, acc);
            float nwc = wc * c0 - ws * s0;
            ws = fmaf(wc, s0, ws * c0);
            wc = nwc;
        }
        cur = (ssp[0] + 2.0f * acc) * (1.0f / 441.0f);
    }

    int im1 = (i == 0) ? (WSZ - 1) : (i - 1);
    float* og = out + (size_t)g * BB * WSZ;
    int nbase = g * BB * WSZ + i;
    for (int b = 0; b < BB; b++) {
        float x = fmaf(fa, sfb[b * WSZ + i], cur);
        float* buf = sx + (b & 1) * WSZ;
        buf[i] = x;
        __syncthreads();
        cur = c * (x + buf[im1]);

        // fused epilogue: fade (last 256 samples), ASR envelope, output gain
        int n = nbase + b * WSZ;
        float v = cur;
        if (n >= N_SAMPLES - 256) v *= fade[n - (N_SAMPLES - 256)];
        float tn = (float)n * (1.0f / SR_F);
        float e1 = fminf(fmaxf(tn * inva, 0.0f), 1.0f);
        float e2 = fminf(fmaxf((T - tn) * invr, 0.0f), 1.0f);
        og[b * WSZ + i] = v * (e1 * e2 * s) * A4;
    }
}

// ---------------- host entry --------------------------------------------
extern "C" void kernel_launch(void* const* d_in, const int* in_sizes, int n_in,
                              void* d_out, int out_size) {
    const float* fb    = (const float*)d_in[0];   // feedback_line [4410000]
    const float* h     = (const float*)d_in[1];   // h [1,9]
    // d_in[2] = t — unused, t[n] == n/44100 exactly in fp32
    const float* noise = (const float*)d_in[3];   // wavetable_noise [441]
    const float* W1    = (const float*)d_in[4];   // [9,128]
    const float* b1    = (const float*)d_in[5];   // [128]
    const float* W2    = (const float*)d_in[6];   // [128,5]
    const float* b2    = (const float*)d_in[7];   // [5]
    const float* lp    = (const float*)d_in[8];   // lp_cutoff [1]
    const float* env   = (const float*)d_in[9];   // env_params [3]
    const float* fade  = (const float*)d_in[10];  // fade [256]
    float* out = (float*)d_out;

    const int dsA = (BB * WSZ + 3 * WSZ) * (int)sizeof(float);            // ~146.4 KB
    const int dsB = (BB * WSZ + 2 * WSZ + 2 * NBIN) * (int)sizeof(float); // ~146.4 KB
    cudaFuncSetAttribute(k_passA, cudaFuncAttributeMaxDynamicSharedMemorySize, dsA);
    cudaFuncSetAttribute(k_passB, cudaFuncAttributeMaxDynamicSharedMemorySize, dsB);

    k_setup<<<1, WSZ>>>(h, noise, W1, b1, W2, b2, lp, env);
    k_passA<<<GG, WSZ, dsA>>>(fb);
    k_scan<<<1, 256>>>();
    k_passB<<<GG, WSZ, dsB>>>(fb, fade, out);
}

// round 4
// speedup vs baseline: 1.9575x; 1.0846x over previous
#include <cuda_runtime.h>
#include <math.h>

// ---------------- problem constants (static in reference) ----------------
#define N_SAMPLES 4410000
#define WSZ       441          // wavetable size
#define BB        80           // chunks per block
#define GG        125          // number of blocks (BB*GG == 10000 chunks)
#define KH        4            // recurrence steps per barrier (halo depth)
#define NG        (BB / KH)    // 20 barrier groups
#define R21       21           // radix (441 = 21*21)

#define PI_F      3.14159265358979f
#define TWOPI_F   6.2831853071795864f
#define SR_F      44100.0f

// ---------------- device scratch ----------------------------------------
__device__ float g_what[2 * WSZ];      // full DFT of wavetable
__device__ float g_lamB[2 * WSZ];      // lambda_m ^ BB (full 441 bins)
__device__ float g_Ehat[GG * 2 * WSZ]; // per-block forced end-state spectra
__device__ float g_Shat[GG * 2 * WSZ]; // per-block entering-state spectra
__device__ float g_scal[8];            // 0:c 1:fa 2:A4 3:inv_a 4:s 5:inv_r 6:T 7:decay

// ---------------- parallel biquad via affine scan (as R3, passing) -------
__device__ void biquad_par(const float* __restrict__ x, float* __restrict__ y,
                           float f, float q, int tid,
                           float* sb1, float* sb2, float (*sMp)[4]) {
    float w0   = (TWOPI_F * f) / SR_F;
    float cosw = cosf(w0);
    float alpha = sinf(w0) / (2.0f * q);
    float b0 = (1.0f - cosw) / 2.0f;
    float b1c = 1.0f - cosw;
    float b2c = (1.0f - cosw) / 2.0f;
    float a0 = 1.0f + alpha;
    float a1 = -2.0f * cosw;
    float a2 = 1.0f - alpha;
    b0 /= a0; b1c /= a0; b2c /= a0; a1 /= a0; a2 /= a0;
    float d1 = b1c - a1 * b0;
    float d2 = b2c - a2 * b0;

    if (tid == 0) {
        float A0 = -a1, A1 = 1.0f, A2 = -a2, A3 = 0.0f;
        #pragma unroll
        for (int dd = 0; dd < 9; dd++) {
            sMp[dd][0] = A0; sMp[dd][1] = A1; sMp[dd][2] = A2; sMp[dd][3] = A3;
            float n0 = A0 * A0 + A1 * A2;
            float n1 = A0 * A1 + A1 * A3;
            float n2 = A2 * A0 + A3 * A2;
            float n3 = A2 * A1 + A3 * A3;
            A0 = n0; A1 = n1; A2 = n2; A3 = n3;
        }
    }
    float xv = x[tid];
    sb1[tid] = xv * d1;
    sb2[tid] = xv * d2;
    __syncthreads();
    #pragma unroll
    for (int dd = 0; dd < 9; dd++) {
        int off = 1 << dd;
        float p1 = 0.0f, p2 = 0.0f;
        if (tid >= off) { p1 = sb1[tid - off]; p2 = sb2[tid - off]; }
        float m0 = sMp[dd][0], m1 = sMp[dd][1], m2 = sMp[dd][2], m3 = sMp[dd][3];
        __syncthreads();
        if (tid >= off) {
            sb1[tid] = fmaf(m0, p1, fmaf(m1, p2, sb1[tid]));
            sb2[tid] = fmaf(m2, p1, fmaf(m3, p2, sb2[tid]));
        }
        __syncthreads();
    }
    float s1 = (tid == 0) ? 0.0f : sb1[tid - 1];
    y[tid] = fmaf(b0, xv, s1);
    __syncthreads();
}

// ---------------- radix-21 forward DFT (smem in, writes global spectrum) --
// E[m] = sum_i x[i] e^{-2 pi i m i/441}; stage1 over i1, stage2 over i0.
__device__ __forceinline__ void dft441_fwd(const float* __restrict__ sx,
                                           float* __restrict__ Gre,
                                           float* __restrict__ Gim,
                                           float* __restrict__ dstRe2,  // global, float2-interleaved base
                                           int tid) {
    // stage 1: tid = m_mod*21 + i0
    {
        int mmod = tid / R21, i0 = tid % R21;
        float ang = -TWOPI_F * (float)mmod / 21.0f;
        float c0, s0; sincosf(ang, &s0, &c0);
        float wc = 1.0f, ws = 0.0f, re = 0.0f, im = 0.0f;
        #pragma unroll
        for (int i1 = 0; i1 < R21; i1++) {
            float v = sx[i0 + R21 * i1];
            re = fmaf(v, wc, re);
            im = fmaf(v, ws, im);
            float nw = wc * c0 - ws * s0;
            ws = fmaf(wc, s0, ws * c0);
            wc = nw;
        }
        Gre[tid] = re; Gim[tid] = im;
    }
    __syncthreads();
    // stage 2: tid = m
    {
        int m = tid, mmod = m % R21;
        float ang = -TWOPI_F * (float)m / 441.0f;
        float c0, s0; sincosf(ang, &s0, &c0);
        float wc = 1.0f, ws = 0.0f, re = 0.0f, im = 0.0f;
        const float* gr = Gre + mmod * R21;
        const float* gi = Gim + mmod * R21;
        #pragma unroll
        for (int i0 = 0; i0 < R21; i0++) {
            float a = gr[i0], b = gi[i0];
            re = fmaf(a, wc, fmaf(-b, ws, re));
            im = fmaf(a, ws, fmaf( b, wc, im));
            float nw = wc * c0 - ws * s0;
            ws = fmaf(wc, s0, ws * c0);
            wc = nw;
        }
        ((float2*)dstRe2)[m] = make_float2(re, im);
    }
}

// ---------------- K1: setup ----------------------------------------------
__global__ __launch_bounds__(WSZ)
void k_setup(const float* __restrict__ h,  const float* __restrict__ noise,
             const float* __restrict__ W1, const float* __restrict__ b1,
             const float* __restrict__ W2, const float* __restrict__ b2,
             const float* __restrict__ lp, const float* __restrict__ env) {
    __shared__ float sh_hidden[128];
    __shared__ float sh_lat[5];
    __shared__ float sx[WSZ];
    __shared__ float sy[WSZ];
    __shared__ float sb1[WSZ];
    __shared__ float sb2[WSZ];
    __shared__ float sMp[9][4];
    int tid = threadIdx.x;

    if (tid < 128) {
        float acc = b1[tid];
        #pragma unroll
        for (int i = 0; i < 9; i++) acc += h[i] * W1[i * 128 + tid];
        sh_hidden[tid] = fmaxf(acc, 0.0f);
    }
    sx[tid] = noise[tid];
    __syncthreads();
    if (tid < 5) {
        float acc = b2[tid];
        for (int j = 0; j < 128; j++) acc += sh_hidden[j] * W2[j * 5 + tid];
        sh_lat[tid] = fmaxf(acc, 0.0f);
    }
    __syncthreads();

    float l0 = sh_lat[0], l1 = sh_lat[1], l2 = sh_lat[2];
    float l3 = sh_lat[3], l4 = sh_lat[4];
    float decay = fminf(fmaxf(l0 / 10.0f + 0.9f, 0.9f), 0.999f);
    float lpf = fminf(fmaxf(l1 * SR_F / 4.0f, 100.0f), SR_F / 2.0f - 1.0f);
    float lpq = fminf(fmaxf(l2, 0.1f), 0.999f);

    biquad_par(sx, sy, lpf, lpq, tid, sb1, sb2, sMp);
    biquad_par(sy, sx, lp[0], 0.707f, tid, sb1, sb2, sMp);
    // sx = wavetable wt

    if (tid == 0) {
        g_scal[0] = decay * 0.5f;
        g_scal[1] = l3;
        g_scal[2] = l4;
        g_scal[3] = 1.0f / (fabsf(env[0]) + 1e-3f);
        g_scal[4] = env[1];
        g_scal[5] = 1.0f / (fabsf(env[2]) + 1e-3f);
        g_scal[6] = (float)(N_SAMPLES - 1) / SR_F;
        g_scal[7] = decay;
    }
    __syncthreads();

    // forward DFT of wt (radix-21) into g_what (reuse sb1/sb2 as stage temp)
    dft441_fwd(sx, sb1, sb2, g_what, tid);

    // lamB: lambda = decay*cos(pi m/441)*e^{-i pi m/441}; BB even -> |rr|^BB
    {
        int m = tid;
        float rr  = decay * cosf((PI_F * (float)m) / 441.0f);
        float mag = powf(fabsf(rr), (float)BB);
        int   k2  = (BB * m) % (2 * WSZ);
        float angp = -(PI_F * (float)k2) / 441.0f;
        float sp, cp; sincosf(angp, &sp, &cp);
        ((float2*)g_lamB)[m] = make_float2(mag * cp, mag * sp);
    }
}

// ---------------- shared recurrence macro body ---------------------------
// Processes NG groups of KH steps. EMIT(j, val) is invoked for each output row.
// ob = double buffer (2*WSZ) holding the "out" state row; sfb = staged fb.

// ---------------- K2: pass A — forced response from zero + forward DFT ---
__global__ __launch_bounds__(WSZ)
void k_passA(const float* __restrict__ fb) {
    extern __shared__ float sm[];
    float* sfb = sm;                   // BB*WSZ
    float* ob  = sm + BB * WSZ;        // 2*WSZ
    float* Gre = ob + 2 * WSZ;         // WSZ
    float* Gim = Gre + WSZ;            // WSZ

    int tid = threadIdx.x;
    int g   = blockIdx.x;
    const float* fbg = fb + (size_t)g * BB * WSZ;
    for (int idx = tid; idx < BB * WSZ; idx += WSZ) sfb[idx] = fbg[idx];
    ob[tid] = 0.0f;                    // initial state = 0
    float c  = g_scal[0];
    float fa = g_scal[1];

    int i = tid;
    int iw[KH + 1];
    #pragma unroll
    for (int m = 0; m <= KH; m++) { int v = i - m; if (v < 0) v += WSZ; iw[m] = v; }
    __syncthreads();

    int cb = 0;
    for (int grp = 0; grp < NG; grp++) {
        int b = grp * KH;
        float O[KH + 1], X[KH + 1];
        const float* obr = ob + cb * WSZ;
        #pragma unroll
        for (int m = 0; m <= KH; m++) O[m] = obr[iw[KH - m]];
        #pragma unroll
        for (int j = 0; j < KH; j++) {
            const float* fr = sfb + (b + j) * WSZ;
            #pragma unroll
            for (int m = j; m <= KH; m++) X[m] = fmaf(fa, fr[iw[KH - m]], O[m]);
            #pragma unroll
            for (int m = KH; m > j; m--) O[m] = c * (X[m] + X[m - 1]);
        }
        ob[(cb ^ 1) * WSZ + i] = O[KH];
        __syncthreads();
        cb ^= 1;
    }

    // forward DFT of end state (radix-21)
    dft441_fwd(ob + cb * WSZ, Gre, Gim, g_Ehat + (size_t)g * 2 * WSZ, tid);
}

// ---------------- K3: sequential scan over blocks (per bin) --------------
__global__ __launch_bounds__(WSZ)
void k_scan() {
    int m = threadIdx.x;
    float2 W = ((const float2*)g_what)[m];
    float2 L = ((const float2*)g_lamB)[m];
    float sre = W.x, sim = W.y;
    float2* Sh = (float2*)g_Shat;
    const float2* Eh = (const float2*)g_Ehat;
    #pragma unroll 5
    for (int g = 0; g < GG; g++) {
        Sh[g * WSZ + m] = make_float2(sre, sim);
        float2 E = Eh[g * WSZ + m];
        float nre = fmaf(L.x, sre, fmaf(-L.y, sim, E.x));
        float nim = fmaf(L.x, sim, fmaf( L.y, sre, E.y));
        sre = nre; sim = nim;
    }
}

// ---------------- K4: pass B — iDFT entering state, recurrence + epilogue -
__global__ __launch_bounds__(WSZ)
void k_passB(const float* __restrict__ fb, const float* __restrict__ fade,
             float* __restrict__ out) {
    extern __shared__ float sm[];
    float* sfb = sm;                   // BB*WSZ
    float* ob  = sm + BB * WSZ;        // 2*WSZ
    float* sre = ob + 2 * WSZ;         // WSZ
    float* sim = sre + WSZ;            // WSZ
    float* Hre = sim + WSZ;            // WSZ
    float* Him = Hre + WSZ;            // WSZ

    int tid = threadIdx.x;
    int g   = blockIdx.x;
    const float* fbg = fb + (size_t)g * BB * WSZ;
    for (int idx = tid; idx < BB * WSZ; idx += WSZ) sfb[idx] = fbg[idx];
    {
        float2 v = ((const float2*)(g_Shat + (size_t)g * 2 * WSZ))[tid];
        sre[tid] = v.x; sim[tid] = v.y;
    }
    float c    = g_scal[0];
    float fa   = g_scal[1];
    float A4   = g_scal[2];
    float inva = g_scal[3];
    float sA   = g_scal[4] * A4;       // s * gain
    float invr = g_scal[5];
    float T    = g_scal[6];
    __syncthreads();

    // inverse DFT (radix-21): x[i] = (1/441) Re{ sum_m S[m] e^{+2pi i m i/441} }
    {   // stage 1: tid = m0*21 + imod
        int m0 = tid / R21, imod = tid % R21;
        float ang = TWOPI_F * (float)imod / 21.0f;
        float c0, s0; sincosf(ang, &s0, &c0);
        float wc = 1.0f, ws = 0.0f, hre = 0.0f, him = 0.0f;
        #pragma unroll
        for (int m1 = 0; m1 < R21; m1++) {
            float a = sre[m0 + R21 * m1];
            float b = sim[m0 + R21 * m1];
            hre = fmaf(a, wc, fmaf(-b, ws, hre));
            him = fmaf(a, ws, fmaf( b, wc, him));
            float nw = wc * c0 - ws * s0;
            ws = fmaf(wc, s0, ws * c0);
            wc = nw;
        }
        Hre[tid] = hre; Him[tid] = him;
    }
    __syncthreads();
    {   // stage 2: tid = i (real part only)
        int i = tid, im21 = i % R21;
        float ang = TWOPI_F * (float)i / 441.0f;
        float c0, s0; sincosf(ang, &s0, &c0);
        float wc = 1.0f, ws = 0.0f, acc = 0.0f;
        #pragma unroll
        for (int m0 = 0; m0 < R21; m0++) {
            float a = Hre[m0 * R21 + im21];
            float b = Him[m0 * R21 + im21];
            acc = fmaf(a, wc, fmaf(-b, ws, acc));
            float nw = wc * c0 - ws * s0;
            ws = fmaf(wc, s0, ws * c0);
            wc = nw;
        }
        ob[i] = acc * (1.0f / 441.0f);
    }

    int i = tid;
    int iw[KH + 1];
    #pragma unroll
    for (int m = 0; m <= KH; m++) { int v = i - m; if (v < 0) v += WSZ; iw[m] = v; }
    __syncthreads();

    int nbase = g * BB * WSZ + i;
    int cb = 0;
    for (int grp = 0; grp < NG; grp++) {
        int b = grp * KH;
        float O[KH + 1], X[KH + 1];
        const float* obr = ob + cb * WSZ;
        #pragma unroll
        for (int m = 0; m <= KH; m++) O[m] = obr[iw[KH - m]];
        #pragma unroll
        for (int j = 0; j < KH; j++) {
            const float* fr = sfb + (b + j) * WSZ;
            #pragma unroll
            for (int m = j; m <= KH; m++) X[m] = fmaf(fa, fr[iw[KH - m]], O[m]);
            #pragma unroll
            for (int m = KH; m > j; m--) O[m] = c * (X[m] + X[m - 1]);

            // fused epilogue for output row b+j
            float v = O[KH];
            int n = nbase + (b + j) * WSZ;
            if (n >= N_SAMPLES - 256) v *= fade[n - (N_SAMPLES - 256)];
            float tn = (float)n * (1.0f / SR_F);
            float e1 = __saturatef(tn * inva);
            float e2 = __saturatef((T - tn) * invr);
            out[n] = v * (e1 * e2) * sA;
        }
        ob[(cb ^ 1) * WSZ + i] = O[KH];
        __syncthreads();
        cb ^= 1;
    }
}

// ---------------- host entry --------------------------------------------
extern "C" void kernel_launch(void* const* d_in, const int* in_sizes, int n_in,
                              void* d_out, int out_size) {
    const float* fb    = (const float*)d_in[0];   // feedback_line [4410000]
    const float* h     = (const float*)d_in[1];   // h [1,9]
    // d_in[2] = t — unused (t[n] == n/44100 exactly in fp32)
    const float* noise = (const float*)d_in[3];   // wavetable_noise [441]
    const float* W1    = (const float*)d_in[4];   // [9,128]
    const float* b1    = (const float*)d_in[5];   // [128]
    const float* W2    = (const float*)d_in[6];   // [128,5]
    const float* b2    = (const float*)d_in[7];   // [5]
    const float* lp    = (const float*)d_in[8];   // lp_cutoff [1]
    const float* env   = (const float*)d_in[9];   // env_params [3]
    const float* fade  = (const float*)d_in[10];  // fade [256]
    float* out = (float*)d_out;

    const int dsA = (BB * WSZ + 4 * WSZ) * (int)sizeof(float);  // 148,176 B
    const int dsB = (BB * WSZ + 6 * WSZ) * (int)sizeof(float);  // 151,704 B
    cudaFuncSetAttribute(k_passA, cudaFuncAttributeMaxDynamicSharedMemorySize, dsA);
    cudaFuncSetAttribute(k_passB, cudaFuncAttributeMaxDynamicSharedMemorySize, dsB);

    k_setup<<<1, WSZ>>>(h, noise, W1, b1, W2, b2, lp, env);
    k_passA<<<GG, WSZ, dsA>>>(fb);
    k_scan<<<1, WSZ>>>();
    k_passB<<<GG, WSZ, dsB>>>(fb, fade, out);
}

// round 6
// speedup vs baseline: 2.1735x; 1.1104x over previous
#include <cuda_runtime.h>
#include <math.h>

// ---------------- problem constants (static in reference) ----------------
#define N_SAMPLES 4410000
#define WSZ       441          // wavetable size
#define BB        80           // chunks per block
#define GG        125          // number of blocks (BB*GG == 10000 chunks)
#define KH        4            // recurrence steps per barrier (halo depth)
#define NG        (BB / KH)    // 20 barrier groups
#define R21       21           // radix (441 = 21*21)

#define PI_F      3.14159265358979f
#define TWOPI_F   6.2831853071795864f
#define SR_F      44100.0f

// ---------------- device scratch ----------------------------------------
__device__ float g_what[2 * WSZ];      // DFT of wavetable
__device__ float g_lamB[2 * WSZ];      // lambda^BB per bin
__device__ float g_Ehat[GG * 2 * WSZ]; // per-block forced end-state spectra
__device__ float g_Shat[GG * 2 * WSZ]; // per-block entering-state spectra
__device__ float g_scal[8];            // 0:c 1:fa 2:sA 3:inv_a 5:inv_r 6:T

// ---------------- parallel biquad via affine scan ------------------------
__device__ void biquad_par(const float* __restrict__ x, float* __restrict__ y,
                           float f, float q, int tid,
                           float* sb1, float* sb2, float (*sMp)[4]) {
    float w0   = (TWOPI_F * f) / SR_F;
    float cosw = cosf(w0);
    float alpha = sinf(w0) / (2.0f * q);
    float b0 = (1.0f - cosw) / 2.0f;
    float b1c = 1.0f - cosw;
    float b2c = (1.0f - cosw) / 2.0f;
    float a0 = 1.0f + alpha;
    float a1 = -2.0f * cosw;
    float a2 = 1.0f - alpha;
    b0 /= a0; b1c /= a0; b2c /= a0; a1 /= a0; a2 /= a0;
    float d1 = b1c - a1 * b0;
    float d2 = b2c - a2 * b0;

    if (tid == 0) {
        float A0 = -a1, A1 = 1.0f, A2 = -a2, A3 = 0.0f;
        #pragma unroll
        for (int dd = 0; dd < 9; dd++) {
            sMp[dd][0] = A0; sMp[dd][1] = A1; sMp[dd][2] = A2; sMp[dd][3] = A3;
            float n0 = A0 * A0 + A1 * A2;
            float n1 = A0 * A1 + A1 * A3;
            float n2 = A2 * A0 + A3 * A2;
            float n3 = A2 * A1 + A3 * A3;
            A0 = n0; A1 = n1; A2 = n2; A3 = n3;
        }
    }
    float xv = x[tid];
    sb1[tid] = xv * d1;
    sb2[tid] = xv * d2;
    __syncthreads();
    #pragma unroll
    for (int dd = 0; dd < 9; dd++) {
        int off = 1 << dd;
        float p1 = 0.0f, p2 = 0.0f;
        if (tid >= off) { p1 = sb1[tid - off]; p2 = sb2[tid - off]; }
        float m0 = sMp[dd][0], m1 = sMp[dd][1], m2 = sMp[dd][2], m3 = sMp[dd][3];
        __syncthreads();
        if (tid >= off) {
            sb1[tid] = fmaf(m0, p1, fmaf(m1, p2, sb1[tid]));
            sb2[tid] = fmaf(m2, p1, fmaf(m3, p2, sb2[tid]));
        }
        __syncthreads();
    }
    float s1 = (tid == 0) ? 0.0f : sb1[tid - 1];
    y[tid] = fmaf(b0, xv, s1);
    __syncthreads();
}

// ---------------- radix-21 forward DFT (smem -> per-thread register bin) --
__device__ __forceinline__ void dft441_fwd_reg(const float* __restrict__ sx,
                                               float* __restrict__ t_re,
                                               float* __restrict__ t_im,
                                               int tid, float* oRe, float* oIm) {
    {   // stage 1: tid = mmod*21 + i0
        int mmod = tid / R21, i0 = tid % R21;
        float ang = -TWOPI_F * (float)mmod / 21.0f;
        float c0, s0; sincosf(ang, &s0, &c0);
        float wc = 1.0f, ws = 0.0f, re = 0.0f, im = 0.0f;
        #pragma unroll
        for (int i1 = 0; i1 < R21; i1++) {
            float v = sx[i0 + R21 * i1];
            re = fmaf(v, wc, re);
            im = fmaf(v, ws, im);
            float nw = wc * c0 - ws * s0;
            ws = fmaf(wc, s0, ws * c0);
            wc = nw;
        }
        t_re[tid] = re; t_im[tid] = im;
    }
    __syncthreads();
    {   // stage 2: tid = m
        int m = tid, mm = m % R21;
        float ang = -TWOPI_F * (float)m / 441.0f;
        float c0, s0; sincosf(ang, &s0, &c0);
        float wc = 1.0f, ws = 0.0f, re = 0.0f, im = 0.0f;
        const float* gr = t_re + mm * R21;
        const float* gi = t_im + mm * R21;
        #pragma unroll
        for (int i0 = 0; i0 < R21; i0++) {
            float a = gr[i0], b = gi[i0];
            re = fmaf(a, wc, fmaf(-b, ws, re));
            im = fmaf(a, ws, fmaf( b, wc, im));
            float nw = wc * c0 - ws * s0;
            ws = fmaf(wc, s0, ws * c0);
            wc = nw;
        }
        *oRe = re; *oIm = im;
    }
    __syncthreads();   // callers reuse the temps after this
}

// ---------------- K_A: setup (redundant per CTA) + pass A -----------------
__global__ __launch_bounds__(WSZ, 1)
void k_passA(const float* __restrict__ fb,   const float* __restrict__ h,
             const float* __restrict__ noise, const float* __restrict__ W1,
             const float* __restrict__ b1,   const float* __restrict__ W2,
             const float* __restrict__ b2,   const float* __restrict__ lp,
             const float* __restrict__ env,  float* __restrict__ out) {
    extern __shared__ float smx[];
    float* sfb = smx;                  // BB*WSZ (fb tile; overwritten with forced rows)
    float* aux = smx + BB * WSZ;       // 6*WSZ scratch

    int tid = threadIdx.x;
    int g   = blockIdx.x;

    // stage fb tile as float4 (BB*WSZ = 8820 float4)
    {
        const float4* f4 = (const float4*)(fb + (size_t)g * BB * WSZ);
        float4* s4 = (float4*)sfb;
        #pragma unroll
        for (int k = 0; k < 20; k++) s4[tid + WSZ * k] = f4[tid + WSZ * k];
    }

    // redundant per-CTA setup
    float* sx   = aux;
    float* sy   = aux + WSZ;
    float* sb1  = aux + 2 * WSZ;
    float* sb2  = aux + 3 * WSZ;
    float* shid = aux + 4 * WSZ;          // 128
    float* slat = aux + 4 * WSZ + 128;    // 5
    float (*sMp)[4] = (float(*)[4])(aux + 4 * WSZ + 160); // 36

    if (tid < 128) {
        float acc = b1[tid];
        #pragma unroll
        for (int i = 0; i < 9; i++) acc += h[i] * W1[i * 128 + tid];
        shid[tid] = fmaxf(acc, 0.0f);
    }
    sx[tid] = noise[tid];
    __syncthreads();
    if (tid < 5) {
        float acc = b2[tid];
        for (int j = 0; j < 128; j++) acc += shid[j] * W2[j * 5 + tid];
        slat[tid] = fmaxf(acc, 0.0f);
    }
    __syncthreads();

    float l0 = slat[0], l1 = slat[1], l2 = slat[2], l3 = slat[3], l4 = slat[4];
    float decay = fminf(fmaxf(l0 / 10.0f + 0.9f, 0.9f), 0.999f);
    float lpf = fminf(fmaxf(l1 * SR_F / 4.0f, 100.0f), SR_F / 2.0f - 1.0f);
    float lpq = fminf(fmaxf(l2, 0.1f), 0.999f);

    biquad_par(sx, sy, lpf, lpq, tid, sb1, sb2, sMp);
    biquad_par(sy, sx, lp[0], 0.707f, tid, sb1, sb2, sMp);
    // sx = wavetable wt

    float c  = decay * 0.5f;
    float fa = l3;

    if (g == 0 && tid == 0) {
        g_scal[0] = c;
        g_scal[1] = fa;
        g_scal[2] = env[1] * l4;                    // s * gain
        g_scal[3] = 1.0f / (fabsf(env[0]) + 1e-3f); // 1/attack
        g_scal[5] = 1.0f / (fabsf(env[2]) + 1e-3f); // 1/release
        g_scal[6] = (float)(N_SAMPLES - 1) / SR_F;  // T == t[-1] exactly (fp32)
    }

    // wavetable DFT + lambda^BB -> global (CTA 0 publishes; all CTAs compute)
    {
        float Wre, Wim;
        dft441_fwd_reg(sx, sb1, sb2, tid, &Wre, &Wim);
        if (g == 0) {
            ((float2*)g_what)[tid] = make_float2(Wre, Wim);
            float rr  = decay * cosf((PI_F * (float)tid) / 441.0f);
            float mag = powf(fabsf(rr), (float)BB);   // BB even -> sign drops
            int   k2  = (BB * tid) % (2 * WSZ);
            float angp = -(PI_F * (float)k2) / 441.0f;
            float sp, cp; sincosf(angp, &sp, &cp);
            ((float2*)g_lamB)[tid] = make_float2(mag * cp, mag * sp);
        }
    }

    int i = tid;
    int iw[KH + 1];
    #pragma unroll
    for (int m = 0; m <= KH; m++) { int v = i - m; if (v < 0) v += WSZ; iw[m] = v; }

    // pass A: forced response from zero; overwrite consumed fb rows in smem
    float* ob = aux;                   // 2*WSZ double buffer
    ob[tid] = 0.0f;
    int cb = 0;
    __syncthreads();

    for (int grp = 0; grp < NG; grp++) {
        int b = grp * KH;
        float O[KH + 1], X[KH + 1], Fout[KH];
        const float* obr = ob + cb * WSZ;
        #pragma unroll
        for (int m = 0; m <= KH; m++) O[m] = obr[iw[KH - m]];
        #pragma unroll
        for (int j = 0; j < KH; j++) {
            const float* fr = sfb + (b + j) * WSZ;
            #pragma unroll
            for (int m = j; m <= KH; m++) X[m] = fmaf(fa, fr[iw[KH - m]], O[m]);
            #pragma unroll
            for (int m = KH; m > j; m--) O[m] = c * (X[m] + X[m - 1]);
            Fout[j] = O[KH];
        }
        ob[(cb ^ 1) * WSZ + i] = O[KH];
        __syncthreads();
        // rows b..b+KH-1 fully consumed by all threads -> safe to overwrite
        #pragma unroll
        for (int j = 0; j < KH; j++) sfb[(b + j) * WSZ + i] = Fout[j];
        cb ^= 1;
    }

    // forward DFT of forced end state -> g_Ehat[g]
    // (dft441_fwd_reg's internal barriers also cover the last sfb overwrite)
    {
        float Ere, Eim;
        dft441_fwd_reg(ob + cb * WSZ, aux + 2 * WSZ, aux + 3 * WSZ, tid, &Ere, &Eim);
        ((float2*)(g_Ehat + (size_t)g * 2 * WSZ))[tid] = make_float2(Ere, Eim);
    }

    // bulk-store forced rows to out (scratch), vectorized
    {
        const float4* s4 = (const float4*)sfb;
        float4* o4 = (float4*)(out + (size_t)g * BB * WSZ);
        #pragma unroll
        for (int k = 0; k < 20; k++) o4[tid + WSZ * k] = s4[tid + WSZ * k];
    }
}

// ---------------- K_scan: sequential scan over blocks (per bin) -----------
__global__ __launch_bounds__(WSZ)
void k_scan() {
    int m = threadIdx.x;
    float2 W = ((const float2*)g_what)[m];
    float2 L = ((const float2*)g_lamB)[m];
    float sre = W.x, sim = W.y;
    float2* Sh = (float2*)g_Shat;
    const float2* Eh = (const float2*)g_Ehat;
    #pragma unroll 5
    for (int g = 0; g < GG; g++) {
        Sh[g * WSZ + m] = make_float2(sre, sim);
        float2 E = Eh[g * WSZ + m];
        float nre = fmaf(L.x, sre, fmaf(-L.y, sim, E.x));
        float nim = fmaf(L.x, sim, fmaf( L.y, sre, E.y));
        sre = nre; sim = nim;
    }
}

// ---------------- K_B: iDFT + homogeneous recurrence + epilogue -----------
__global__ __launch_bounds__(WSZ, 1)
void k_passB(const float* __restrict__ fade, float* __restrict__ out) {
    extern __shared__ float smx[];
    float* sfb = smx;                  // BB*WSZ (forced rows, from out scratch)
    float* aux = smx + BB * WSZ;       // 6*WSZ

    int tid = threadIdx.x;
    int g   = blockIdx.x;

    // stage forced rows (float4)
    {
        const float4* f4 = (const float4*)(out + (size_t)g * BB * WSZ);
        float4* s4 = (float4*)sfb;
        #pragma unroll
        for (int k = 0; k < 20; k++) s4[tid + WSZ * k] = f4[tid + WSZ * k];
    }

    float* ob  = aux;                  // 2*WSZ
    float* sre = aux + 2 * WSZ;
    float* sim = aux + 3 * WSZ;
    float* Hre = aux + 4 * WSZ;
    float* Him = aux + 5 * WSZ;

    {
        float2 v = ((const float2*)(g_Shat + (size_t)g * 2 * WSZ))[tid];
        sre[tid] = v.x; sim[tid] = v.y;
    }
    float c    = g_scal[0];
    float sA   = g_scal[2];
    float inva = g_scal[3];
    float invr = g_scal[5];
    float T    = g_scal[6];
    __syncthreads();

    // inverse DFT (radix-21): x[i] = (1/441) Re{ sum_m S[m] e^{+2pi i m i/441} }
    int i = tid;
    {   // stage 1: tid = m0*21 + imod
        int m0 = tid / R21, imod = tid % R21;
        float ang = TWOPI_F * (float)imod / 21.0f;
        float c0, s0; sincosf(ang, &s0, &c0);
        float wc = 1.0f, ws = 0.0f, hre = 0.0f, him = 0.0f;
        #pragma unroll
        for (int m1 = 0; m1 < R21; m1++) {
            float a = sre[m0 + R21 * m1];
            float b = sim[m0 + R21 * m1];
            hre = fmaf(a, wc, fmaf(-b, ws, hre));
            him = fmaf(a, ws, fmaf( b, wc, him));
            float nw = wc * c0 - ws * s0;
            ws = fmaf(wc, s0, ws * c0);
            wc = nw;
        }
        Hre[tid] = hre; Him[tid] = him;
    }
    __syncthreads();
    {   // stage 2: tid = i (real part only)
        int im21 = i % R21;
        float ang = TWOPI_F * (float)i / 441.0f;
        float c0, s0; sincosf(ang, &s0, &c0);
        float wc = 1.0f, ws = 0.0f, acc = 0.0f;
        #pragma unroll
        for (int m0 = 0; m0 < R21; m0++) {
            float a = Hre[m0 * R21 + im21];
            float b = Him[m0 * R21 + im21];
            acc = fmaf(a, wc, fmaf(-b, ws, acc));
            float nw = wc * c0 - ws * s0;
            ws = fmaf(wc, s0, ws * c0);
            wc = nw;
        }
        ob[i] = acc * (1.0f / 441.0f);
    }
    __syncthreads();

    int iw[KH + 1];
    #pragma unroll
    for (int m = 0; m <= KH; m++) { int v = i - m; if (v < 0) v += WSZ; iw[m] = v; }

    // homogeneous recurrence; out = homog + forced(row)
    int nbase = g * BB * WSZ + i;
    int cb = 0;
    for (int grp = 0; grp < NG; grp++) {
        int b = grp * KH;
        float O[KH + 1];
        const float* obr = ob + cb * WSZ;
        #pragma unroll
        for (int m = 0; m <= KH; m++) O[m] = obr[iw[KH - m]];
        #pragma unroll
        for (int j = 0; j < KH; j++) {
            #pragma unroll
            for (int m = KH; m > j; m--) O[m] = c * (O[m] + O[m - 1]);

            float v = O[KH] + sfb[(b + j) * WSZ + i];
            int n = nbase + (b + j) * WSZ;
            if (n >= N_SAMPLES - 256) v *= fade[n - (N_SAMPLES - 256)];
            float tn = (float)n * (1.0f / SR_F);
            float e1 = __saturatef(tn * inva);
            float e2 = __saturatef((T - tn) * invr);
            out[n] = v * (e1 * e2) * sA;
        }
        ob[(cb ^ 1) * WSZ + i] = O[KH];
        __syncthreads();
        cb ^= 1;
    }
}

// ---------------- host entry --------------------------------------------
extern "C" void kernel_launch(void* const* d_in, const int* in_sizes, int n_in,
                              void* d_out, int out_size) {
    const float* fb    = (const float*)d_in[0];   // feedback_line [4410000]
    const float* h     = (const float*)d_in[1];   // h [1,9]
    // d_in[2] = t — unused (t[n] == n/44100 exactly in fp32)
    const float* noise = (const float*)d_in[3];   // wavetable_noise [441]
    const float* W1    = (const float*)d_in[4];   // [9,128]
    const float* b1    = (const float*)d_in[5];   // [128]
    const float* W2    = (const float*)d_in[6];   // [128,5]
    const float* b2    = (const float*)d_in[7];   // [5]
    const float* lp    = (const float*)d_in[8];   // lp_cutoff [1]
    const float* env   = (const float*)d_in[9];   // env_params [3]
    const float* fade  = (const float*)d_in[10];  // fade [256]
    float* out = (float*)d_out;

    const int ds = (BB * WSZ + 6 * WSZ) * (int)sizeof(float);  // 151,704 B
    cudaFuncSetAttribute(k_passA, cudaFuncAttributeMaxDynamicSharedMemorySize, ds);
    cudaFuncSetAttribute(k_passB, cudaFuncAttributeMaxDynamicSharedMemorySize, ds);

    k_passA<<<GG, WSZ, ds>>>(fb, h, noise, W1, b1, W2, b2, lp, env, out);
    k_scan<<<1, WSZ>>>();
    k_passB<<<GG, WSZ, ds>>>(fade, out);
}